// round 13
// baseline (speedup 1.0000x reference)
#include <cuda_runtime.h>
#include <cuda_fp16.h>
#include <cstdint>

#define Bd 128
#define Sd 2048
#define Hd 256
#define Ed 256
#define VSZ 32000
#define NCH 32                              // 64-row S-chunks per batch
#define NVB 125                             // vocab blocks of 256

// ---------------- scratch (device globals; no allocation) ----------------
__device__ float g_w2h[Bd * Hd];
__device__ float g_mz[2 * Bd * NCH];
__device__ float g_XaP[NCH * Bd * Hd];
__device__ float g_cat[Bd * 512];
__device__ float g_res[Bd * Hd];
__device__ float g_gi[Bd * 768];            // cell 0 gates
__device__ float g_gh[Bd * 768];
__device__ float g_gi2[Bd * 768];           // cell 1 gates
__device__ float g_gh2[Bd * 768];
__device__ float g_lmz[Bd * NVB * 2];
__device__ __align__(16) __half g_h1h[Bd * Hd];

#define PAD_E 72
#define CH_HALF_E (Hd * PAD_E)              // 36864 B per chunk
__device__ __align__(16) __half g_W1p[4 * CH_HALF_E];
__device__ __align__(16) __half g_Woutp[4 * VSZ * PAD_E];

// ---------------- helpers ----------------
__device__ __forceinline__ float fast_tanh(float x) {
    float y;
    asm("tanh.approx.f32 %0, %1;" : "=f"(y) : "f"(x));
    return y;
}
__device__ __forceinline__ uint32_t smem_u32(const void* p) {
    uint32_t a;
    asm("{ .reg .u64 t; cvta.to.shared.u64 t, %1; cvt.u32.u64 %0, t; }"
        : "=r"(a) : "l"(p));
    return a;
}
__device__ __forceinline__ void cp16(uint32_t dst, const void* src) {
    asm volatile("cp.async.cg.shared.global [%0], [%1], 16;"
                 :: "r"(dst), "l"(src) : "memory");
}
__device__ __forceinline__ void cp_commit() {
    asm volatile("cp.async.commit_group;" ::: "memory");
}
template <int N>
__device__ __forceinline__ void cp_wait() {
    asm volatile("cp.async.wait_group %0;" :: "n"(N) : "memory");
}
__device__ __forceinline__ void mma_fp16(float* d, const uint32_t* a,
                                         uint32_t b0, uint32_t b1) {
    asm volatile(
        "mma.sync.aligned.m16n8k16.row.col.f32.f16.f16.f32 "
        "{%0,%1,%2,%3}, {%4,%5,%6,%7}, {%8,%9}, {%0,%1,%2,%3};"
        : "+f"(d[0]), "+f"(d[1]), "+f"(d[2]), "+f"(d[3])
        : "r"(a[0]), "r"(a[1]), "r"(a[2]), "r"(a[3]), "r"(b0), "r"(b1));
}
__device__ __forceinline__ void ldsm_x4(uint32_t* r, uint32_t addr) {
    asm volatile(
        "ldmatrix.sync.aligned.m8n8.x4.shared.b16 {%0,%1,%2,%3}, [%4];"
        : "=r"(r[0]), "=r"(r[1]), "=r"(r[2]), "=r"(r[3]) : "r"(addr));
}

// ---------------- K0: prep (W1 pack | w2h) --------------------------------
// grid: [0,256) W1 pack; [256,288) w2h slices.
__global__ __launch_bounds__(256)
void prep_kernel(const float* __restrict__ W1,
                 const float* __restrict__ hidden,
                 const float* __restrict__ W2,
                 const float* __restrict__ b2) {
    const int bid = blockIdx.x;
    const int tid = threadIdx.x;
    if (bid < 256) {
        int n = bid;
        int k = tid;
        float x = W1[k * Hd + n];
        g_W1p[(k >> 6) * CH_HALF_E + n * PAD_E + (k & 63)] = __float2half_rn(x);
    } else {
        int wb = bid - 256;
        int n0 = (wb & 3) * 64;
        int b0 = (wb >> 2) * 16;
        __shared__ float sh[16][260];
        for (int i = tid; i < 16 * 256; i += 256) {
            int bb = i >> 8;
            int k = i & 255;
            sh[bb][k] = hidden[(size_t)(Bd + b0 + bb) * Hd + k];
        }
        __syncthreads();
        int nn = tid & 63;
        int bq = tid >> 6;
        float acc[4] = {0.f, 0.f, 0.f, 0.f};
#pragma unroll 8
        for (int j = 0; j < 256; j++) {
            float w = W2[j * Hd + n0 + nn];
#pragma unroll
            for (int u = 0; u < 4; u++) acc[u] += sh[bq + 4 * u][j] * w;
        }
        float bias = b2[n0 + nn];
#pragma unroll
        for (int u = 0; u < 4; u++)
            g_w2h[(size_t)(b0 + bq + 4 * u) * Hd + n0 + nn] = acc[u] + bias;
    }
}

// ---------------- K2: scores (+ Wout pack folded in) ----------------------
#define SA_HI 0
#define SB_OFF 33792
#define SB_STRIDE 36864
#define SC_SMEM (33792 + 2 * 36864)
__global__ __launch_bounds__(256, 2)
void scores_mma_kernel(const float* __restrict__ enc,
                       const float* __restrict__ Vv,
                       const float* __restrict__ Wout) {
    extern __shared__ __align__(16) char smem[];
    const uint32_t sm_b = smem_u32(smem);
    const int tid = threadIdx.x;
    const int wid = tid >> 5;
    const int lane = tid & 31;
    const int g = lane >> 2;
    const int t = lane & 3;
    const int wm = wid >> 2;
    const int wn = wid & 3;
    const int quad = lane >> 3;
    const int r8 = lane & 7;
    const int b = blockIdx.x >> 5;
    const int chunk = blockIdx.x & (NCH - 1);
    const int m0 = blockIdx.x * 64;
    const float* encb = enc + (size_t)m0 * Hd;

    // ---- folded Wout fp16 pack (2 float4 per thread) ----
#pragma unroll
    for (int i = 0; i < 2; i++) {
        int gidx = (blockIdx.x * 2 + i) * 256 + tid;
        if (gidx < (VSZ * Hd / 4)) {
            int idx4 = gidx * 4;
            int v = idx4 >> 8;
            int k = idx4 & 255;
            float4 x = *(const float4*)(Wout + (size_t)v * Hd + k);
            __half2 a = {__float2half_rn(x.x), __float2half_rn(x.y)};
            __half2 bb2 = {__float2half_rn(x.z), __float2half_rn(x.w)};
            uint2 w;
            w.x = *(uint32_t*)&a;
            w.y = *(uint32_t*)&bb2;
            *(uint2*)&g_Woutp[(size_t)(k >> 6) * VSZ * PAD_E +
                              (size_t)v * PAD_E + (k & 63)] = w;
        }
    }

    uint32_t aaddr[2];
#pragma unroll
    for (int f = 0; f < 2; f++)
        aaddr[f] = sm_b + (wm * 32 + f * 16 + ((quad & 1) << 3) + r8) * 528
                 + ((quad >> 1) << 4);
    uint32_t bbase[4];
#pragma unroll
    for (int jj = 0; jj < 4; jj++)
        bbase[jj] = (wn * 64 + jj * 16 + ((quad >> 1) << 3) + r8) * 144
                  + ((quad & 1) << 4);

    {
        const char* src = (const char*)g_W1p;
#pragma unroll
        for (int i = 0; i < 9; i++) {
            int idx = tid + i * 256;
            cp16(sm_b + SB_OFF + idx * 16, src + idx * 16);
        }
        cp_commit();
    }
    {
#pragma unroll
        for (int i = 0; i < 16; i++) {
            int idx = tid + i * 256;
            int row = idx >> 6;
            int kp = idx & 63;
            float4 v = *(const float4*)(encb + (size_t)row * Hd + kp * 4);
            __half2 h0 = {__float2half_rn(v.x), __float2half_rn(v.y)};
            __half2 h1 = {__float2half_rn(v.z), __float2half_rn(v.w)};
            uint2 w;
            w.x = *(uint32_t*)&h0;
            w.y = *(uint32_t*)&h1;
            *(uint2*)(smem + SA_HI + row * 528 + kp * 8) = w;
        }
    }

    float acc[2][8][4];
#pragma unroll
    for (int f = 0; f < 2; f++)
#pragma unroll
        for (int j = 0; j < 8; j++)
#pragma unroll
            for (int q = 0; q < 4; q++) acc[f][j][q] = 0.f;

#pragma unroll
    for (int c = 0; c < 4; c++) {
        if (c < 3) {
            const char* src = (const char*)(g_W1p + (size_t)(c + 1) * CH_HALF_E);
            uint32_t dst = sm_b + SB_OFF + ((c + 1) & 1) * SB_STRIDE;
#pragma unroll
            for (int i = 0; i < 9; i++) {
                int idx = tid + i * 256;
                cp16(dst + idx * 16, src + idx * 16);
            }
            cp_commit();
            cp_wait<1>();
        } else {
            cp_wait<0>();
        }
        __syncthreads();

        const uint32_t buf = sm_b + SB_OFF + (c & 1) * SB_STRIDE;
#pragma unroll
        for (int ks = 0; ks < 4; ks++) {
            uint32_t af[2][4];
#pragma unroll
            for (int f = 0; f < 2; f++)
                ldsm_x4(af[f], aaddr[f] + c * 128 + ks * 32);
#pragma unroll
            for (int jj = 0; jj < 4; jj++) {
                uint32_t bf[4];
                ldsm_x4(bf, buf + bbase[jj] + ks * 32);
                mma_fp16(acc[0][2 * jj], af[0], bf[0], bf[1]);
                mma_fp16(acc[1][2 * jj], af[1], bf[0], bf[1]);
                mma_fp16(acc[0][2 * jj + 1], af[0], bf[2], bf[3]);
                mma_fp16(acc[1][2 * jj + 1], af[1], bf[2], bf[3]);
            }
        }
        __syncthreads();
    }

    float* EP = (float*)(smem + SB_OFF);
    float* sw2 = EP;
    float* sV = EP + 256;
    float* sp = EP + 512;
    float* red = EP + 768;
    float* e_arr = EP + 832;
    sw2[tid] = g_w2h[b * Hd + tid];
    sV[tid] = Vv[tid];
    __syncthreads();

    float p[2][2] = {{0.f, 0.f}, {0.f, 0.f}};
#pragma unroll
    for (int f = 0; f < 2; f++)
#pragma unroll
        for (int j = 0; j < 8; j++) {
            int cc = wn * 64 + 8 * j + 2 * t;
            float v0 = sV[cc], v1 = sV[cc + 1];
            float w0 = sw2[cc], w1 = sw2[cc + 1];
            p[f][0] += v0 * fast_tanh(acc[f][j][0] + w0)
                     + v1 * fast_tanh(acc[f][j][1] + w1);
            p[f][1] += v0 * fast_tanh(acc[f][j][2] + w0)
                     + v1 * fast_tanh(acc[f][j][3] + w1);
        }
#pragma unroll
    for (int f = 0; f < 2; f++)
#pragma unroll
        for (int u = 0; u < 2; u++) {
            float v = p[f][u];
            v += __shfl_xor_sync(0xffffffffu, v, 1);
            v += __shfl_xor_sync(0xffffffffu, v, 2);
            if (t == 0) {
                int r = wm * 32 + f * 16 + g + 8 * u;
                sp[wn * 64 + r] = v;
            }
        }
    __syncthreads();

    float sc = 0.f;
    if (tid < 64) {
        sc = sp[tid] + sp[64 + tid] + sp[128 + tid] + sp[192 + tid];
        red[tid] = sc;
    }
    __syncthreads();
    for (int d = 32; d > 0; d >>= 1) {
        if (tid < d) red[tid] = fmaxf(red[tid], red[tid + d]);
        __syncthreads();
    }
    float mloc = red[0];
    __syncthreads();
    if (tid < 64) {
        float e = expf(sc - mloc);
        e_arr[tid] = e;
        red[tid] = e;
    }
    __syncthreads();
    for (int d = 32; d > 0; d >>= 1) {
        if (tid < d) red[tid] += red[tid + d];
        __syncthreads();
    }
    if (tid == 0) {
        g_mz[2 * blockIdx.x] = mloc;
        g_mz[2 * blockIdx.x + 1] = red[0];
    }
    __syncthreads();

    float a2 = 0.f;
#pragma unroll 8
    for (int s = 0; s < 64; s++) {
        __half hv = *(const __half*)(smem + SA_HI + s * 528 + tid * 2);
        a2 += e_arr[s] * __half2float(hv);
    }
    g_XaP[((size_t)chunk * Bd + b) * Hd + tid] = a2;
}

// ---------------- K3: cat = [emb[inp]; Xa-combined] ----------------
__global__ void cat_kernel(const int* __restrict__ inp,
                           const float* __restrict__ emb) {
    const int b = blockIdx.x;
    const int tid = threadIdx.x;  // 256
    int token = inp[b];
    g_cat[b * 512 + tid] = emb[(size_t)token * Ed + tid];
    float M = -1e30f;
#pragma unroll
    for (int i = 0; i < NCH; i++)
        M = fmaxf(M, g_mz[2 * (b * NCH + i)]);
    float Z = 0.f, X = 0.f;
#pragma unroll
    for (int i = 0; i < NCH; i++) {
        float w = expf(g_mz[2 * (b * NCH + i)] - M);
        Z += w * g_mz[2 * (b * NCH + i) + 1];
        X += w * g_XaP[((size_t)i * Bd + b) * Hd + tid];
    }
    g_cat[b * 512 + 256 + tid] = X / Z;
}

// ---------------- K4: res = cat @ W3 + b3 (128 CTAs: 16n x 8b) ------------
#define RES_SMEM ((16 * 524 + 16 * 520) * 4)
__global__ __launch_bounds__(256)
void res_kernel(const float* __restrict__ W3, const float* __restrict__ b3) {
    extern __shared__ float rsm[];
    float* w3t = rsm;                // 16 x 524 [n][k]
    float* cs = rsm + 16 * 524;      // 16 x 520 [b][k]
    const int n0 = (blockIdx.x & 15) * 16;
    const int bt = blockIdx.x >> 4;
    const int tid = threadIdx.x;
    const int nn = tid & 15;
    const int bq = tid >> 4;         // 0..15

    // W3 fill: float4 over n, scatter to transposed smem
    for (int idx = tid; idx < 2048; idx += 256) {
        int k = idx >> 2;
        int u = idx & 3;
        float4 w = *(const float4*)(W3 + (size_t)k * Hd + n0 + u * 4);
        w3t[(u * 4 + 0) * 524 + k] = w.x;
        w3t[(u * 4 + 1) * 524 + k] = w.y;
        w3t[(u * 4 + 2) * 524 + k] = w.z;
        w3t[(u * 4 + 3) * 524 + k] = w.w;
    }
    // cat fill: coalesced
    for (int idx = tid; idx < 16 * 512; idx += 256) {
        int bb = idx >> 9;
        int k = idx & 511;
        cs[bb * 520 + k] = g_cat[(size_t)(bt * 16 + bb) * 512 + k];
    }
    __syncthreads();

    float a0 = 0.f, a1 = 0.f, a2 = 0.f, a3 = 0.f;
#pragma unroll 8
    for (int k4 = 0; k4 < 128; k4++) {
        float4 cv = *(const float4*)&cs[bq * 520 + k4 * 4];
        float4 wv = *(const float4*)&w3t[nn * 524 + k4 * 4];
        a0 += cv.x * wv.x;
        a1 += cv.y * wv.y;
        a2 += cv.z * wv.z;
        a3 += cv.w * wv.w;
    }
    g_res[(size_t)(bt * 16 + bq) * Hd + n0 + nn] =
        (a0 + a1) + (a2 + a3) + b3[n0 + nn];
}

// ---------------- K5: GRU gate GEMVs; cell 1 inlines combine0 -------------
__global__ __launch_bounds__(512)
void gru_gates_kernel(const float* __restrict__ hidden,
                      const float* __restrict__ Wih,
                      const float* __restrict__ Whh,
                      const float* __restrict__ bih,
                      const float* __restrict__ bhh,
                      int cell,
                      float* __restrict__ hid_out) {
    const int n0 = blockIdx.x * 64;
    const int b0 = blockIdx.y * 16;
    const int tid = threadIdx.x;
    __shared__ float xs[16][260], hs[16][260];
    if (cell == 0) {
        for (int i = tid; i < 16 * 256; i += 512) {
            int bb = i >> 8;
            int k = i & 255;
            xs[bb][k] = g_res[(size_t)(b0 + bb) * Hd + k];
            hs[bb][k] = hidden[(size_t)(b0 + bb) * Hd + k];
        }
    } else {
        for (int i = tid; i < 16 * 256; i += 512) {
            int bb = i >> 8;
            int j = i & 255;
            int b = b0 + bb;
            float gir = g_gi[(size_t)b * 768 + j];
            float ghr = g_gh[(size_t)b * 768 + j];
            float giz = g_gi[(size_t)b * 768 + 256 + j];
            float ghz = g_gh[(size_t)b * 768 + 256 + j];
            float gin = g_gi[(size_t)b * 768 + 512 + j];
            float ghn = g_gh[(size_t)b * 768 + 512 + j];
            float r = 1.f / (1.f + expf(-(gir + ghr)));
            float z = 1.f / (1.f + expf(-(giz + ghz)));
            float n = tanhf(gin + r * ghn);
            float h = hidden[(size_t)b * Hd + j];
            float hn = (1.f - z) * n + z * h;
            xs[bb][j] = hn;
            hs[bb][j] = hidden[(size_t)(Bd + b) * Hd + j];
            if (blockIdx.x == 0) hid_out[(size_t)b * Hd + j] = hn;
        }
    }
    __syncthreads();
    const int bb = tid & 15;
    const int g2 = tid >> 4;
    float* gi_out = (cell == 0) ? g_gi : g_gi2;
    float* gh_out = (cell == 0) ? g_gh : g_gh2;
#pragma unroll
    for (int gg = 0; gg < 2; gg++) {
        int gr = n0 + g2 + gg * 32;
        const float4* wi = (const float4*)(Wih + (size_t)gr * Hd);
        const float4* wh = (const float4*)(Whh + (size_t)gr * Hd);
        float gi = bih[gr], gh = bhh[gr];
#pragma unroll 8
        for (int k4 = 0; k4 < 64; k4++) {
            float4 a = wi[k4];
            float4 c = wh[k4];
            float4 xv = *(const float4*)&xs[bb][k4 * 4];
            float4 hv = *(const float4*)&hs[bb][k4 * 4];
            gi += a.x * xv.x + a.y * xv.y + a.z * xv.z + a.w * xv.w;
            gh += c.x * hv.x + c.y * hv.y + c.z * hv.z + c.w * hv.w;
        }
        gi_out[(size_t)(b0 + bb) * 768 + gr] = gi;
        gh_out[(size_t)(b0 + bb) * 768 + gr] = gh;
    }
}

// ---------------- K6: combine cell 1 -> hid_out + fp16 h1 ----------------
__global__ void gru_combine1_kernel(const float* __restrict__ hidden,
                                    float* __restrict__ hid_out) {
    int idx = blockIdx.x * 512 + threadIdx.x;  // 32768
    int b = idx >> 8;
    int j = idx & 255;
    float gir = g_gi2[(size_t)b * 768 + j];
    float ghr = g_gh2[(size_t)b * 768 + j];
    float giz = g_gi2[(size_t)b * 768 + 256 + j];
    float ghz = g_gh2[(size_t)b * 768 + 256 + j];
    float gin = g_gi2[(size_t)b * 768 + 512 + j];
    float ghn = g_gh2[(size_t)b * 768 + 512 + j];
    float r = 1.f / (1.f + expf(-(gir + ghr)));
    float z = 1.f / (1.f + expf(-(giz + ghz)));
    float n = tanhf(gin + r * ghn);
    float h = hidden[(size_t)(Bd + b) * Hd + j];
    float hn = (1.f - z) * n + z * h;
    hid_out[(size_t)(Bd + b) * Hd + j] = hn;
    g_h1h[(size_t)b * Hd + j] = __float2half_rn(hn);
}

// ---------------- K7: logits via fp16 mma + ldmatrix + softmax partials ---
#define LSB_OFF 67584
#define LG_SMEM (67584 + 2 * 36864)
__global__ __launch_bounds__(512, 1)
void logits_mma_kernel(const float* __restrict__ bout,
                       float* __restrict__ out) {
    extern __shared__ __align__(16) char smem[];
    const uint32_t sm_b = smem_u32(smem);
    const int tid = threadIdx.x;
    const int wid = tid >> 5;
    const int lane = tid & 31;
    const int g = lane >> 2;
    const int t = lane & 3;
    const int wm = wid >> 2;
    const int wn = wid & 3;
    const int quad = lane >> 3;
    const int r8 = lane & 7;
    const int v0 = blockIdx.x * 256;

    float acc[2][8][4];
#pragma unroll
    for (int f = 0; f < 2; f++)
#pragma unroll
        for (int j = 0; j < 8; j++)
#pragma unroll
            for (int q = 0; q < 4; q++) acc[f][j][q] = 0.f;

    uint32_t aaddr[2];
#pragma unroll
    for (int f = 0; f < 2; f++)
        aaddr[f] = sm_b + (wm * 32 + f * 16 + ((quad & 1) << 3) + r8) * 528
                 + ((quad >> 1) << 4);
    uint32_t bbase[4];
#pragma unroll
    for (int jj = 0; jj < 4; jj++)
        bbase[jj] = (wn * 64 + jj * 16 + ((quad >> 1) << 3) + r8) * 144
                  + ((quad & 1) << 4);

    {
        const char* src = (const char*)(g_Woutp + (size_t)v0 * PAD_E);
#pragma unroll
        for (int i = 0; i < 5; i++) {
            int idx = tid + i * 512;
            if (idx < 2304) cp16(sm_b + LSB_OFF + idx * 16, src + idx * 16);
        }
        cp_commit();
    }
    {
        const uint32_t* src = (const uint32_t*)g_h1h;
#pragma unroll
        for (int i = 0; i < 32; i++) {
            int idx = tid + i * 512;
            int row = idx >> 7;
            int c32 = idx & 127;
            *(uint32_t*)(smem + row * 528 + c32 * 4) = src[idx];
        }
    }

#pragma unroll
    for (int c = 0; c < 4; c++) {
        if (c < 3) {
            const char* src =
                (const char*)(g_Woutp + ((size_t)(c + 1) * VSZ + v0) * PAD_E);
            uint32_t dst = sm_b + LSB_OFF + ((c + 1) & 1) * SB_STRIDE;
#pragma unroll
            for (int i = 0; i < 5; i++) {
                int idx = tid + i * 512;
                if (idx < 2304) cp16(dst + idx * 16, src + idx * 16);
            }
            cp_commit();
            cp_wait<1>();
        } else {
            cp_wait<0>();
        }
        __syncthreads();

        const uint32_t buf = sm_b + LSB_OFF + (c & 1) * SB_STRIDE;
#pragma unroll
        for (int ks = 0; ks < 4; ks++) {
            uint32_t af[2][4];
#pragma unroll
            for (int f = 0; f < 2; f++)
                ldsm_x4(af[f], aaddr[f] + c * 128 + ks * 32);
#pragma unroll
            for (int jj = 0; jj < 4; jj++) {
                uint32_t bf[4];
                ldsm_x4(bf, buf + bbase[jj] + ks * 32);
                mma_fp16(acc[0][2 * jj], af[0], bf[0], bf[1]);
                mma_fp16(acc[1][2 * jj], af[1], bf[0], bf[1]);
                mma_fp16(acc[0][2 * jj + 1], af[0], bf[2], bf[3]);
                mma_fp16(acc[1][2 * jj + 1], af[1], bf[2], bf[3]);
            }
        }
        __syncthreads();
    }

    float* stage = (float*)(smem + LSB_OFF);
    float rm = -1e30f, rs = 0.f;
#pragma unroll
    for (int cg = 0; cg < 4; cg++) {
        if (wn == cg) {
#pragma unroll
            for (int f = 0; f < 2; f++)
#pragma unroll
                for (int j = 0; j < 8; j++)
#pragma unroll
                    for (int q = 0; q < 4; q++) {
                        int row = wm * 32 + f * 16 + g + 8 * (q >> 1);
                        int col = 8 * j + 2 * t + (q & 1);
                        stage[row * 65 + col] = acc[f][j][q];
                    }
        }
        __syncthreads();
#pragma unroll
        for (int i = 0; i < 16; i++) {
            int idx = tid + i * 512;
            int row = idx >> 6;
            int col = idx & 63;
            out[(size_t)row * VSZ + v0 + cg * 64 + col] =
                stage[row * 65 + col] + bout[v0 + cg * 64 + col];
        }
        if (tid < 128) {
            float lm = rm;
            for (int col = 0; col < 64; col++)
                lm = fmaxf(lm, stage[tid * 65 + col] + bout[v0 + cg * 64 + col]);
            float sc = rs * expf(rm - lm);
            for (int col = 0; col < 64; col++)
                sc += expf(stage[tid * 65 + col] + bout[v0 + cg * 64 + col] - lm);
            rm = lm;
            rs = sc;
        }
        __syncthreads();
    }
    if (tid < 128) {
        g_lmz[(tid * NVB + blockIdx.x) * 2] = rm;
        g_lmz[(tid * NVB + blockIdx.x) * 2 + 1] = rs;
    }
}

// ---------------- K8: log_softmax via partials (single pass) --------------
__global__ __launch_bounds__(1024)
void logsoftmax_kernel(float* __restrict__ out) {
    const int b = blockIdx.x;
    const int tid = threadIdx.x;
    __shared__ float red[1024];
    float4* row4 = (float4*)(out + (size_t)b * VSZ);

    float lm = -1e30f;
    if (tid < NVB) lm = g_lmz[(b * NVB + tid) * 2];
    red[tid] = lm;
    __syncthreads();
    for (int d = 512; d > 0; d >>= 1) {
        if (tid < d) red[tid] = fmaxf(red[tid], red[tid + d]);
        __syncthreads();
    }
    float M = red[0];
    __syncthreads();
    float sv = 0.f;
    if (tid < NVB)
        sv = g_lmz[(b * NVB + tid) * 2 + 1] * expf(lm - M);
    red[tid] = sv;
    __syncthreads();
    for (int d = 512; d > 0; d >>= 1) {
        if (tid < d) red[tid] += red[tid + d];
        __syncthreads();
    }
    float lse = M + logf(red[0]);
    for (int v = tid; v < 8000; v += 1024) {
        float4 x = row4[v];
        x.x -= lse; x.y -= lse; x.z -= lse; x.w -= lse;
        row4[v] = x;
    }
}

// ---------------- launch ----------------
extern "C" void kernel_launch(void* const* d_in, const int* in_sizes, int n_in,
                              void* d_out, int out_size) {
    const int* inp = (const int*)d_in[0];
    const float* hidden = (const float*)d_in[1];
    const float* enc = (const float*)d_in[2];
    const float* emb = (const float*)d_in[3];
    const float* W1 = (const float*)d_in[4];
    const float* W2 = (const float*)d_in[5];
    const float* W3 = (const float*)d_in[6];
    const float* b2 = (const float*)d_in[7];
    const float* b3 = (const float*)d_in[8];
    const float* V = (const float*)d_in[9];
    const float* Wih0 = (const float*)d_in[10];
    const float* Whh0 = (const float*)d_in[11];
    const float* bih0 = (const float*)d_in[12];
    const float* bhh0 = (const float*)d_in[13];
    const float* Wih1 = (const float*)d_in[14];
    const float* Whh1 = (const float*)d_in[15];
    const float* bih1 = (const float*)d_in[16];
    const float* bhh1 = (const float*)d_in[17];
    const float* Wout = (const float*)d_in[18];
    const float* bout = (const float*)d_in[19];

    float* out = (float*)d_out;
    float* hid_out = out + (size_t)Bd * VSZ;

    cudaFuncSetAttribute(scores_mma_kernel,
                         cudaFuncAttributeMaxDynamicSharedMemorySize, SC_SMEM);
    cudaFuncSetAttribute(logits_mma_kernel,
                         cudaFuncAttributeMaxDynamicSharedMemorySize, LG_SMEM);
    cudaFuncSetAttribute(res_kernel,
                         cudaFuncAttributeMaxDynamicSharedMemorySize, RES_SMEM);

    prep_kernel<<<288, 256>>>(W1, hidden, W2, b2);
    scores_mma_kernel<<<Bd * NCH, 256, SC_SMEM>>>(enc, V, Wout);
    cat_kernel<<<Bd, 256>>>(inp, emb);
    res_kernel<<<128, 256, RES_SMEM>>>(W3, b3);
    gru_gates_kernel<<<dim3(12, 8), 512>>>(hidden, Wih0, Whh0, bih0, bhh0,
                                           0, hid_out);
    gru_gates_kernel<<<dim3(12, 8), 512>>>(hidden, Wih1, Whh1, bih1, bhh1,
                                           1, hid_out);
    gru_combine1_kernel<<<64, 512>>>(hidden, hid_out);
    logits_mma_kernel<<<NVB, 512, LG_SMEM>>>(bout, out);
    logsoftmax_kernel<<<Bd, 1024>>>(out);
}

// round 15
// speedup vs baseline: 1.0372x; 1.0372x over previous
#include <cuda_runtime.h>
#include <cuda_fp16.h>
#include <cstdint>

#define Bd 128
#define Sd 2048
#define Hd 256
#define Ed 256
#define VSZ 32000
#define NCH 32                              // 64-row S-chunks per batch
#define NVB 125                             // vocab blocks of 256

// ---------------- scratch (device globals; no allocation) ----------------
__device__ float g_w2h[Bd * Hd];
__device__ float g_mz[2 * Bd * NCH];
__device__ float g_XaP[NCH * Bd * Hd];
__device__ float g_cat[Bd * 512];
__device__ float g_res[Bd * Hd];
__device__ float g_gi[Bd * 768];            // cell 0 gates
__device__ float g_gh[Bd * 768];
__device__ float g_gi2[Bd * 768];           // cell 1 gates
__device__ float g_gh2[Bd * 768];
__device__ float g_lmz[Bd * NVB * 2];
__device__ __align__(16) __half g_h1h[Bd * Hd];

#define PAD_E 72
#define CH_HALF_E (Hd * PAD_E)              // 36864 B per chunk
__device__ __align__(16) __half g_W1p[4 * CH_HALF_E];
__device__ __align__(16) __half g_Woutp[4 * VSZ * PAD_E];

// ---------------- helpers ----------------
__device__ __forceinline__ float fast_tanh(float x) {
    float y;
    asm("tanh.approx.f32 %0, %1;" : "=f"(y) : "f"(x));
    return y;
}
__device__ __forceinline__ uint32_t smem_u32(const void* p) {
    uint32_t a;
    asm("{ .reg .u64 t; cvta.to.shared.u64 t, %1; cvt.u32.u64 %0, t; }"
        : "=r"(a) : "l"(p));
    return a;
}
__device__ __forceinline__ void cp16(uint32_t dst, const void* src) {
    asm volatile("cp.async.cg.shared.global [%0], [%1], 16;"
                 :: "r"(dst), "l"(src) : "memory");
}
__device__ __forceinline__ void cp_commit() {
    asm volatile("cp.async.commit_group;" ::: "memory");
}
template <int N>
__device__ __forceinline__ void cp_wait() {
    asm volatile("cp.async.wait_group %0;" :: "n"(N) : "memory");
}
__device__ __forceinline__ void mma_fp16(float* d, const uint32_t* a,
                                         uint32_t b0, uint32_t b1) {
    asm volatile(
        "mma.sync.aligned.m16n8k16.row.col.f32.f16.f16.f32 "
        "{%0,%1,%2,%3}, {%4,%5,%6,%7}, {%8,%9}, {%0,%1,%2,%3};"
        : "+f"(d[0]), "+f"(d[1]), "+f"(d[2]), "+f"(d[3])
        : "r"(a[0]), "r"(a[1]), "r"(a[2]), "r"(a[3]), "r"(b0), "r"(b1));
}
__device__ __forceinline__ void ldsm_x4(uint32_t* r, uint32_t addr) {
    asm volatile(
        "ldmatrix.sync.aligned.m8n8.x4.shared.b16 {%0,%1,%2,%3}, [%4];"
        : "=r"(r[0]), "=r"(r[1]), "=r"(r[2]), "=r"(r[3]) : "r"(addr));
}

// ---------------- K0: merged prep (Wout pack | W1 pack | w2h) -------------
// grid: [0,8000) wout pack; [8000,8256) W1 pack; [8256,8288) w2h slices.
__global__ __launch_bounds__(256)
void prep_merge_kernel(const float* __restrict__ W1,
                       const float* __restrict__ Wout,
                       const float* __restrict__ hidden,
                       const float* __restrict__ W2,
                       const float* __restrict__ b2) {
    const int bid = blockIdx.x;
    const int tid = threadIdx.x;
    if (bid < 8000) {
        int idx4 = (bid * 256 + tid) * 4;
        int v = idx4 >> 8;
        int k = idx4 & 255;
        float4 x = *(const float4*)(Wout + (size_t)v * Hd + k);
        __half2 a = {__float2half_rn(x.x), __float2half_rn(x.y)};
        __half2 b = {__float2half_rn(x.z), __float2half_rn(x.w)};
        uint2 w;
        w.x = *(uint32_t*)&a;
        w.y = *(uint32_t*)&b;
        *(uint2*)&g_Woutp[(size_t)(k >> 6) * VSZ * PAD_E +
                          (size_t)v * PAD_E + (k & 63)] = w;
    } else if (bid < 8256) {
        int n = bid - 8000;
        int k = tid;
        float x = W1[k * Hd + n];
        g_W1p[(k >> 6) * CH_HALF_E + n * PAD_E + (k & 63)] = __float2half_rn(x);
    } else {
        int wb = bid - 8256;
        int n0 = (wb & 3) * 64;
        int b0 = (wb >> 2) * 16;
        __shared__ float sh[16][260];
        for (int i = tid; i < 16 * 256; i += 256) {
            int bb = i >> 8;
            int k = i & 255;
            sh[bb][k] = hidden[(size_t)(Bd + b0 + bb) * Hd + k];
        }
        __syncthreads();
        int nn = tid & 63;
        int bq = tid >> 6;
        float acc[4] = {0.f, 0.f, 0.f, 0.f};
#pragma unroll 8
        for (int j = 0; j < 256; j++) {
            float w = W2[j * Hd + n0 + nn];
#pragma unroll
            for (int u = 0; u < 4; u++) acc[u] += sh[bq + 4 * u][j] * w;
        }
        float bias = b2[n0 + nn];
#pragma unroll
        for (int u = 0; u < 4; u++)
            g_w2h[(size_t)(b0 + bq + 4 * u) * Hd + n0 + nn] = acc[u] + bias;
    }
}

// ---------------- K2: scores + local softmax + partial Xa numerator -------
#define SA_HI 0
#define SB_OFF 33792
#define SB_STRIDE 36864
#define SC_SMEM (33792 + 2 * 36864)
__global__ __launch_bounds__(256, 2)
void scores_mma_kernel(const float* __restrict__ enc,
                       const float* __restrict__ Vv) {
    extern __shared__ __align__(16) char smem[];
    const uint32_t sm_b = smem_u32(smem);
    const int tid = threadIdx.x;
    const int wid = tid >> 5;
    const int lane = tid & 31;
    const int g = lane >> 2;
    const int t = lane & 3;
    const int wm = wid >> 2;
    const int wn = wid & 3;
    const int quad = lane >> 3;
    const int r8 = lane & 7;
    const int b = blockIdx.x >> 5;
    const int chunk = blockIdx.x & (NCH - 1);
    const int m0 = blockIdx.x * 64;
    const float* encb = enc + (size_t)m0 * Hd;

    float acc[2][8][4];
#pragma unroll
    for (int f = 0; f < 2; f++)
#pragma unroll
        for (int j = 0; j < 8; j++)
#pragma unroll
            for (int q = 0; q < 4; q++) acc[f][j][q] = 0.f;

    uint32_t aaddr[2];
#pragma unroll
    for (int f = 0; f < 2; f++)
        aaddr[f] = sm_b + (wm * 32 + f * 16 + ((quad & 1) << 3) + r8) * 528
                 + ((quad >> 1) << 4);
    uint32_t bbase[4];
#pragma unroll
    for (int jj = 0; jj < 4; jj++)
        bbase[jj] = (wn * 64 + jj * 16 + ((quad >> 1) << 3) + r8) * 144
                  + ((quad & 1) << 4);

    {
        const char* src = (const char*)g_W1p;
#pragma unroll
        for (int i = 0; i < 9; i++) {
            int idx = tid + i * 256;
            cp16(sm_b + SB_OFF + idx * 16, src + idx * 16);
        }
        cp_commit();
    }
    {
#pragma unroll
        for (int i = 0; i < 16; i++) {
            int idx = tid + i * 256;
            int row = idx >> 6;
            int kp = idx & 63;
            float4 v = *(const float4*)(encb + (size_t)row * Hd + kp * 4);
            __half2 h0 = {__float2half_rn(v.x), __float2half_rn(v.y)};
            __half2 h1 = {__float2half_rn(v.z), __float2half_rn(v.w)};
            uint2 w;
            w.x = *(uint32_t*)&h0;
            w.y = *(uint32_t*)&h1;
            *(uint2*)(smem + SA_HI + row * 528 + kp * 8) = w;
        }
    }

#pragma unroll
    for (int c = 0; c < 4; c++) {
        if (c < 3) {
            const char* src = (const char*)(g_W1p + (size_t)(c + 1) * CH_HALF_E);
            uint32_t dst = sm_b + SB_OFF + ((c + 1) & 1) * SB_STRIDE;
#pragma unroll
            for (int i = 0; i < 9; i++) {
                int idx = tid + i * 256;
                cp16(dst + idx * 16, src + idx * 16);
            }
            cp_commit();
            cp_wait<1>();
        } else {
            cp_wait<0>();
        }
        __syncthreads();

        const uint32_t buf = sm_b + SB_OFF + (c & 1) * SB_STRIDE;
#pragma unroll
        for (int ks = 0; ks < 4; ks++) {
            uint32_t af[2][4];
#pragma unroll
            for (int f = 0; f < 2; f++)
                ldsm_x4(af[f], aaddr[f] + c * 128 + ks * 32);
#pragma unroll
            for (int jj = 0; jj < 4; jj++) {
                uint32_t bf[4];
                ldsm_x4(bf, buf + bbase[jj] + ks * 32);
                mma_fp16(acc[0][2 * jj], af[0], bf[0], bf[1]);
                mma_fp16(acc[1][2 * jj], af[1], bf[0], bf[1]);
                mma_fp16(acc[0][2 * jj + 1], af[0], bf[2], bf[3]);
                mma_fp16(acc[1][2 * jj + 1], af[1], bf[2], bf[3]);
            }
        }
        __syncthreads();
    }

    float* EP = (float*)(smem + SB_OFF);
    float* sw2 = EP;
    float* sV = EP + 256;
    float* sp = EP + 512;
    float* red = EP + 768;
    float* e_arr = EP + 832;
    sw2[tid] = g_w2h[b * Hd + tid];
    sV[tid] = Vv[tid];
    __syncthreads();

    float p[2][2] = {{0.f, 0.f}, {0.f, 0.f}};
#pragma unroll
    for (int f = 0; f < 2; f++)
#pragma unroll
        for (int j = 0; j < 8; j++) {
            int cc = wn * 64 + 8 * j + 2 * t;
            float v0 = sV[cc], v1 = sV[cc + 1];
            float w0 = sw2[cc], w1 = sw2[cc + 1];
            p[f][0] += v0 * fast_tanh(acc[f][j][0] + w0)
                     + v1 * fast_tanh(acc[f][j][1] + w1);
            p[f][1] += v0 * fast_tanh(acc[f][j][2] + w0)
                     + v1 * fast_tanh(acc[f][j][3] + w1);
        }
#pragma unroll
    for (int f = 0; f < 2; f++)
#pragma unroll
        for (int u = 0; u < 2; u++) {
            float v = p[f][u];
            v += __shfl_xor_sync(0xffffffffu, v, 1);
            v += __shfl_xor_sync(0xffffffffu, v, 2);
            if (t == 0) {
                int r = wm * 32 + f * 16 + g + 8 * u;
                sp[wn * 64 + r] = v;
            }
        }
    __syncthreads();

    float sc = 0.f;
    if (tid < 64) {
        sc = sp[tid] + sp[64 + tid] + sp[128 + tid] + sp[192 + tid];
        red[tid] = sc;
    }
    __syncthreads();
    for (int d = 32; d > 0; d >>= 1) {
        if (tid < d) red[tid] = fmaxf(red[tid], red[tid + d]);
        __syncthreads();
    }
    float mloc = red[0];
    __syncthreads();
    if (tid < 64) {
        float e = expf(sc - mloc);
        e_arr[tid] = e;
        red[tid] = e;
    }
    __syncthreads();
    for (int d = 32; d > 0; d >>= 1) {
        if (tid < d) red[tid] += red[tid + d];
        __syncthreads();
    }
    if (tid == 0) {
        g_mz[2 * blockIdx.x] = mloc;
        g_mz[2 * blockIdx.x + 1] = red[0];
    }
    __syncthreads();

    float a2 = 0.f;
#pragma unroll 8
    for (int s = 0; s < 64; s++) {
        __half hv = *(const __half*)(smem + SA_HI + s * 528 + tid * 2);
        a2 += e_arr[s] * __half2float(hv);
    }
    g_XaP[((size_t)chunk * Bd + b) * Hd + tid] = a2;
}

// ---------------- K3: cat = [emb[inp]; Xa-combined] ----------------
__global__ void cat_kernel(const int* __restrict__ inp,
                           const float* __restrict__ emb) {
    const int b = blockIdx.x;
    const int tid = threadIdx.x;  // 256
    int token = inp[b];
    g_cat[b * 512 + tid] = emb[(size_t)token * Ed + tid];
    float M = -1e30f;
#pragma unroll
    for (int i = 0; i < NCH; i++)
        M = fmaxf(M, g_mz[2 * (b * NCH + i)]);
    float Z = 0.f, X = 0.f;
#pragma unroll
    for (int i = 0; i < NCH; i++) {
        float w = expf(g_mz[2 * (b * NCH + i)] - M);
        Z += w * g_mz[2 * (b * NCH + i) + 1];
        X += w * g_XaP[((size_t)i * Bd + b) * Hd + tid];
    }
    g_cat[b * 512 + 256 + tid] = X / Z;
}

// ---------------- K4: res = cat @ W3 + b3 (128 CTAs: 16n x 8b) ------------
#define RES_SMEM ((16 * 524 + 16 * 520) * 4)
__global__ __launch_bounds__(256)
void res_kernel(const float* __restrict__ W3, const float* __restrict__ b3) {
    extern __shared__ float rsm[];
    float* w3t = rsm;                // 16 x 524 [n][k]
    float* cs = rsm + 16 * 524;      // 16 x 520 [b][k]
    const int n0 = (blockIdx.x & 15) * 16;
    const int bt = blockIdx.x >> 4;
    const int tid = threadIdx.x;
    const int nn = tid & 15;
    const int bq = tid >> 4;         // 0..15

    for (int idx = tid; idx < 2048; idx += 256) {
        int k = idx >> 2;
        int u = idx & 3;
        float4 w = *(const float4*)(W3 + (size_t)k * Hd + n0 + u * 4);
        w3t[(u * 4 + 0) * 524 + k] = w.x;
        w3t[(u * 4 + 1) * 524 + k] = w.y;
        w3t[(u * 4 + 2) * 524 + k] = w.z;
        w3t[(u * 4 + 3) * 524 + k] = w.w;
    }
    for (int idx = tid; idx < 16 * 512; idx += 256) {
        int bb = idx >> 9;
        int k = idx & 511;
        cs[bb * 520 + k] = g_cat[(size_t)(bt * 16 + bb) * 512 + k];
    }
    __syncthreads();

    float a0 = 0.f, a1 = 0.f, a2 = 0.f, a3 = 0.f;
#pragma unroll 8
    for (int k4 = 0; k4 < 128; k4++) {
        float4 cv = *(const float4*)&cs[bq * 520 + k4 * 4];
        float4 wv = *(const float4*)&w3t[nn * 524 + k4 * 4];
        a0 += cv.x * wv.x;
        a1 += cv.y * wv.y;
        a2 += cv.z * wv.z;
        a3 += cv.w * wv.w;
    }
    g_res[(size_t)(bt * 16 + bq) * Hd + n0 + nn] =
        (a0 + a1) + (a2 + a3) + b3[n0 + nn];
}

// ---------------- K5: GRU gate GEMVs; cell 1 inlines combine0 -------------
__global__ __launch_bounds__(512)
void gru_gates_kernel(const float* __restrict__ hidden,
                      const float* __restrict__ Wih,
                      const float* __restrict__ Whh,
                      const float* __restrict__ bih,
                      const float* __restrict__ bhh,
                      int cell,
                      float* __restrict__ hid_out) {
    const int n0 = blockIdx.x * 64;
    const int b0 = blockIdx.y * 16;
    const int tid = threadIdx.x;
    __shared__ float xs[16][260], hs[16][260];
    if (cell == 0) {
        for (int i = tid; i < 16 * 256; i += 512) {
            int bb = i >> 8;
            int k = i & 255;
            xs[bb][k] = g_res[(size_t)(b0 + bb) * Hd + k];
            hs[bb][k] = hidden[(size_t)(b0 + bb) * Hd + k];
        }
    } else {
        for (int i = tid; i < 16 * 256; i += 512) {
            int bb = i >> 8;
            int j = i & 255;
            int b = b0 + bb;
            float gir = g_gi[(size_t)b * 768 + j];
            float ghr = g_gh[(size_t)b * 768 + j];
            float giz = g_gi[(size_t)b * 768 + 256 + j];
            float ghz = g_gh[(size_t)b * 768 + 256 + j];
            float gin = g_gi[(size_t)b * 768 + 512 + j];
            float ghn = g_gh[(size_t)b * 768 + 512 + j];
            float r = 1.f / (1.f + expf(-(gir + ghr)));
            float z = 1.f / (1.f + expf(-(giz + ghz)));
            float n = tanhf(gin + r * ghn);
            float h = hidden[(size_t)b * Hd + j];
            float hn = (1.f - z) * n + z * h;
            xs[bb][j] = hn;
            hs[bb][j] = hidden[(size_t)(Bd + b) * Hd + j];
            if (blockIdx.x == 0) hid_out[(size_t)b * Hd + j] = hn;
        }
    }
    __syncthreads();
    const int bb = tid & 15;
    const int g2 = tid >> 4;
    float* gi_out = (cell == 0) ? g_gi : g_gi2;
    float* gh_out = (cell == 0) ? g_gh : g_gh2;
#pragma unroll
    for (int gg = 0; gg < 2; gg++) {
        int gr = n0 + g2 + gg * 32;
        const float4* wi = (const float4*)(Wih + (size_t)gr * Hd);
        const float4* wh = (const float4*)(Whh + (size_t)gr * Hd);
        float gi = bih[gr], gh = bhh[gr];
#pragma unroll 8
        for (int k4 = 0; k4 < 64; k4++) {
            float4 a = wi[k4];
            float4 c = wh[k4];
            float4 xv = *(const float4*)&xs[bb][k4 * 4];
            float4 hv = *(const float4*)&hs[bb][k4 * 4];
            gi += a.x * xv.x + a.y * xv.y + a.z * xv.z + a.w * xv.w;
            gh += c.x * hv.x + c.y * hv.y + c.z * hv.z + c.w * hv.w;
        }
        gi_out[(size_t)(b0 + bb) * 768 + gr] = gi;
        gh_out[(size_t)(b0 + bb) * 768 + gr] = gh;
    }
}

// ---------------- K6: combine cell 1 -> hid_out + fp16 h1 ----------------
__global__ void gru_combine1_kernel(const float* __restrict__ hidden,
                                    float* __restrict__ hid_out) {
    int idx = blockIdx.x * 512 + threadIdx.x;  // 32768
    int b = idx >> 8;
    int j = idx & 255;
    float gir = g_gi2[(size_t)b * 768 + j];
    float ghr = g_gh2[(size_t)b * 768 + j];
    float giz = g_gi2[(size_t)b * 768 + 256 + j];
    float ghz = g_gh2[(size_t)b * 768 + 256 + j];
    float gin = g_gi2[(size_t)b * 768 + 512 + j];
    float ghn = g_gh2[(size_t)b * 768 + 512 + j];
    float r = 1.f / (1.f + expf(-(gir + ghr)));
    float z = 1.f / (1.f + expf(-(giz + ghz)));
    float n = tanhf(gin + r * ghn);
    float h = hidden[(size_t)(Bd + b) * Hd + j];
    float hn = (1.f - z) * n + z * h;
    hid_out[(size_t)(Bd + b) * Hd + j] = hn;
    g_h1h[(size_t)b * Hd + j] = __float2half_rn(hn);
}

// ---------------- K7: logits via fp16 mma + ldmatrix + softmax partials ---
#define LSB_OFF 67584
#define LG_SMEM (67584 + 2 * 36864)
__global__ __launch_bounds__(512, 1)
void logits_mma_kernel(const float* __restrict__ bout,
                       float* __restrict__ out) {
    extern __shared__ __align__(16) char smem[];
    const uint32_t sm_b = smem_u32(smem);
    const int tid = threadIdx.x;
    const int wid = tid >> 5;
    const int lane = tid & 31;
    const int g = lane >> 2;
    const int t = lane & 3;
    const int wm = wid >> 2;
    const int wn = wid & 3;
    const int quad = lane >> 3;
    const int r8 = lane & 7;
    const int v0 = blockIdx.x * 256;

    float acc[2][8][4];
#pragma unroll
    for (int f = 0; f < 2; f++)
#pragma unroll
        for (int j = 0; j < 8; j++)
#pragma unroll
            for (int q = 0; q < 4; q++) acc[f][j][q] = 0.f;

    uint32_t aaddr[2];
#pragma unroll
    for (int f = 0; f < 2; f++)
        aaddr[f] = sm_b + (wm * 32 + f * 16 + ((quad & 1) << 3) + r8) * 528
                 + ((quad >> 1) << 4);
    uint32_t bbase[4];
#pragma unroll
    for (int jj = 0; jj < 4; jj++)
        bbase[jj] = (wn * 64 + jj * 16 + ((quad >> 1) << 3) + r8) * 144
                  + ((quad & 1) << 4);

    {
        const char* src = (const char*)(g_Woutp + (size_t)v0 * PAD_E);
#pragma unroll
        for (int i = 0; i < 5; i++) {
            int idx = tid + i * 512;
            if (idx < 2304) cp16(sm_b + LSB_OFF + idx * 16, src + idx * 16);
        }
        cp_commit();
    }
    {
        const uint32_t* src = (const uint32_t*)g_h1h;
#pragma unroll
        for (int i = 0; i < 32; i++) {
            int idx = tid + i * 512;
            int row = idx >> 7;
            int c32 = idx & 127;
            *(uint32_t*)(smem + row * 528 + c32 * 4) = src[idx];
        }
    }

#pragma unroll
    for (int c = 0; c < 4; c++) {
        if (c < 3) {
            const char* src =
                (const char*)(g_Woutp + ((size_t)(c + 1) * VSZ + v0) * PAD_E);
            uint32_t dst = sm_b + LSB_OFF + ((c + 1) & 1) * SB_STRIDE;
#pragma unroll
            for (int i = 0; i < 5; i++) {
                int idx = tid + i * 512;
                if (idx < 2304) cp16(dst + idx * 16, src + idx * 16);
            }
            cp_commit();
            cp_wait<1>();
        } else {
            cp_wait<0>();
        }
        __syncthreads();

        const uint32_t buf = sm_b + LSB_OFF + (c & 1) * SB_STRIDE;
#pragma unroll
        for (int ks = 0; ks < 4; ks++) {
            uint32_t af[2][4];
#pragma unroll
            for (int f = 0; f < 2; f++)
                ldsm_x4(af[f], aaddr[f] + c * 128 + ks * 32);
#pragma unroll
            for (int jj = 0; jj < 4; jj++) {
                uint32_t bf[4];
                ldsm_x4(bf, buf + bbase[jj] + ks * 32);
                mma_fp16(acc[0][2 * jj], af[0], bf[0], bf[1]);
                mma_fp16(acc[1][2 * jj], af[1], bf[0], bf[1]);
                mma_fp16(acc[0][2 * jj + 1], af[0], bf[2], bf[3]);
                mma_fp16(acc[1][2 * jj + 1], af[1], bf[2], bf[3]);
            }
        }
        __syncthreads();
    }

    float* stage = (float*)(smem + LSB_OFF);
    float rm = -1e30f, rs = 0.f;
#pragma unroll
    for (int cg = 0; cg < 4; cg++) {
        if (wn == cg) {
#pragma unroll
            for (int f = 0; f < 2; f++)
#pragma unroll
                for (int j = 0; j < 8; j++)
#pragma unroll
                    for (int q = 0; q < 4; q++) {
                        int row = wm * 32 + f * 16 + g + 8 * (q >> 1);
                        int col = 8 * j + 2 * t + (q & 1);
                        stage[row * 65 + col] = acc[f][j][q];
                    }
        }
        __syncthreads();
#pragma unroll
        for (int i = 0; i < 16; i++) {
            int idx = tid + i * 512;
            int row = idx >> 6;
            int col = idx & 63;
            out[(size_t)row * VSZ + v0 + cg * 64 + col] =
                stage[row * 65 + col] + bout[v0 + cg * 64 + col];
        }
        if (tid < 128) {
            float lm = rm;
            for (int col = 0; col < 64; col++)
                lm = fmaxf(lm, stage[tid * 65 + col] + bout[v0 + cg * 64 + col]);
            float sc = rs * expf(rm - lm);
            for (int col = 0; col < 64; col++)
                sc += expf(stage[tid * 65 + col] + bout[v0 + cg * 64 + col] - lm);
            rm = lm;
            rs = sc;
        }
        __syncthreads();
    }
    if (tid < 128) {
        g_lmz[(tid * NVB + blockIdx.x) * 2] = rm;
        g_lmz[(tid * NVB + blockIdx.x) * 2 + 1] = rs;
    }
}

// ---------------- K8: log_softmax via partials (single pass) --------------
__global__ __launch_bounds__(1024)
void logsoftmax_kernel(float* __restrict__ out) {
    const int b = blockIdx.x;
    const int tid = threadIdx.x;
    __shared__ float red[1024];
    float4* row4 = (float4*)(out + (size_t)b * VSZ);

    float lm = -1e30f;
    if (tid < NVB) lm = g_lmz[(b * NVB + tid) * 2];
    red[tid] = lm;
    __syncthreads();
    for (int d = 512; d > 0; d >>= 1) {
        if (tid < d) red[tid] = fmaxf(red[tid], red[tid + d]);
        __syncthreads();
    }
    float M = red[0];
    __syncthreads();
    float sv = 0.f;
    if (tid < NVB)
        sv = g_lmz[(b * NVB + tid) * 2 + 1] * expf(lm - M);
    red[tid] = sv;
    __syncthreads();
    for (int d = 512; d > 0; d >>= 1) {
        if (tid < d) red[tid] += red[tid + d];
        __syncthreads();
    }
    float lse = M + logf(red[0]);
    for (int v = tid; v < 8000; v += 1024) {
        float4 x = row4[v];
        x.x -= lse; x.y -= lse; x.z -= lse; x.w -= lse;
        row4[v] = x;
    }
}

// ---------------- launch ----------------
extern "C" void kernel_launch(void* const* d_in, const int* in_sizes, int n_in,
                              void* d_out, int out_size) {
    const int* inp = (const int*)d_in[0];
    const float* hidden = (const float*)d_in[1];
    const float* enc = (const float*)d_in[2];
    const float* emb = (const float*)d_in[3];
    const float* W1 = (const float*)d_in[4];
    const float* W2 = (const float*)d_in[5];
    const float* W3 = (const float*)d_in[6];
    const float* b2 = (const float*)d_in[7];
    const float* b3 = (const float*)d_in[8];
    const float* V = (const float*)d_in[9];
    const float* Wih0 = (const float*)d_in[10];
    const float* Whh0 = (const float*)d_in[11];
    const float* bih0 = (const float*)d_in[12];
    const float* bhh0 = (const float*)d_in[13];
    const float* Wih1 = (const float*)d_in[14];
    const float* Whh1 = (const float*)d_in[15];
    const float* bih1 = (const float*)d_in[16];
    const float* bhh1 = (const float*)d_in[17];
    const float* Wout = (const float*)d_in[18];
    const float* bout = (const float*)d_in[19];

    float* out = (float*)d_out;
    float* hid_out = out + (size_t)Bd * VSZ;

    cudaFuncSetAttribute(scores_mma_kernel,
                         cudaFuncAttributeMaxDynamicSharedMemorySize, SC_SMEM);
    cudaFuncSetAttribute(logits_mma_kernel,
                         cudaFuncAttributeMaxDynamicSharedMemorySize, LG_SMEM);
    cudaFuncSetAttribute(res_kernel,
                         cudaFuncAttributeMaxDynamicSharedMemorySize, RES_SMEM);

    prep_merge_kernel<<<8288, 256>>>(W1, Wout, hidden, W2, b2);
    scores_mma_kernel<<<Bd * NCH, 256, SC_SMEM>>>(enc, V);
    cat_kernel<<<Bd, 256>>>(inp, emb);
    res_kernel<<<128, 256, RES_SMEM>>>(W3, b3);
    gru_gates_kernel<<<dim3(12, 8), 512>>>(hidden, Wih0, Whh0, bih0, bhh0,
                                           0, hid_out);
    gru_gates_kernel<<<dim3(12, 8), 512>>>(hidden, Wih1, Whh1, bih1, bhh1,
                                           1, hid_out);
    gru_combine1_kernel<<<64, 512>>>(hidden, hid_out);
    logits_mma_kernel<<<NVB, 512, LG_SMEM>>>(bout, out);
    logsoftmax_kernel<<<Bd, 1024>>>(out);
}

// round 16
// speedup vs baseline: 1.0432x; 1.0058x over previous
#include <cuda_runtime.h>
#include <cuda_fp16.h>
#include <cstdint>

#define Bd 128
#define Sd 2048
#define Hd 256
#define Ed 256
#define VSZ 32000
#define NCH 32                              // 64-row S-chunks per batch
#define NVB 125                             // vocab blocks of 256

// ---------------- scratch (device globals; no allocation) ----------------
__device__ float g_w2h[Bd * Hd];
__device__ float g_mz[2 * Bd * NCH];
__device__ float g_XaP[NCH * Bd * Hd];
__device__ float g_cat[Bd * 512];
__device__ float g_res[Bd * Hd];
__device__ float g_gi[Bd * 768];            // cell 0 gates
__device__ float g_gh[Bd * 768];
__device__ float g_gi2[Bd * 768];           // cell 1 gates
__device__ float g_gh2[Bd * 768];
__device__ float g_lmz[Bd * NVB * 2];
__device__ __align__(16) __half g_h1h[Bd * Hd];

#define PAD_E 72
#define CH_HALF_E (Hd * PAD_E)              // 36864 B per chunk
__device__ __align__(16) __half g_W1p[4 * CH_HALF_E];
__device__ __align__(16) __half g_Woutp[4 * VSZ * PAD_E];

// ---------------- helpers ----------------
__device__ __forceinline__ float fast_tanh(float x) {
    float y;
    asm("tanh.approx.f32 %0, %1;" : "=f"(y) : "f"(x));
    return y;
}
__device__ __forceinline__ uint32_t smem_u32(const void* p) {
    uint32_t a;
    asm("{ .reg .u64 t; cvta.to.shared.u64 t, %1; cvt.u32.u64 %0, t; }"
        : "=r"(a) : "l"(p));
    return a;
}
__device__ __forceinline__ void cp16(uint32_t dst, const void* src) {
    asm volatile("cp.async.cg.shared.global [%0], [%1], 16;"
                 :: "r"(dst), "l"(src) : "memory");
}
__device__ __forceinline__ void cp_commit() {
    asm volatile("cp.async.commit_group;" ::: "memory");
}
template <int N>
__device__ __forceinline__ void cp_wait() {
    asm volatile("cp.async.wait_group %0;" :: "n"(N) : "memory");
}
__device__ __forceinline__ void mma_fp16(float* d, const uint32_t* a,
                                         uint32_t b0, uint32_t b1) {
    asm volatile(
        "mma.sync.aligned.m16n8k16.row.col.f32.f16.f16.f32 "
        "{%0,%1,%2,%3}, {%4,%5,%6,%7}, {%8,%9}, {%0,%1,%2,%3};"
        : "+f"(d[0]), "+f"(d[1]), "+f"(d[2]), "+f"(d[3])
        : "r"(a[0]), "r"(a[1]), "r"(a[2]), "r"(a[3]), "r"(b0), "r"(b1));
}
__device__ __forceinline__ void ldsm_x4(uint32_t* r, uint32_t addr) {
    asm volatile(
        "ldmatrix.sync.aligned.m8n8.x4.shared.b16 {%0,%1,%2,%3}, [%4];"
        : "=r"(r[0]), "=r"(r[1]), "=r"(r[2]), "=r"(r[3]) : "r"(addr));
}

// ---------------- K0: merged prep (Wout pack | W1 pack | w2h) -------------
// grid: [0,4000) wout pack (2 float4/thread); [4000,4256) W1 pack;
//       [4256,4288) w2h slices.
__global__ __launch_bounds__(256)
void prep_merge_kernel(const float* __restrict__ W1,
                       const float* __restrict__ Wout,
                       const float* __restrict__ hidden,
                       const float* __restrict__ W2,
                       const float* __restrict__ b2) {
    const int bid = blockIdx.x;
    const int tid = threadIdx.x;
    if (bid < 4000) {
#pragma unroll
        for (int r = 0; r < 2; r++) {
            int idx4 = ((bid * 2 + r) * 256 + tid) * 4;
            int v = idx4 >> 8;
            int k = idx4 & 255;
            float4 x = *(const float4*)(Wout + (size_t)v * Hd + k);
            __half2 a = {__float2half_rn(x.x), __float2half_rn(x.y)};
            __half2 b = {__float2half_rn(x.z), __float2half_rn(x.w)};
            uint2 w;
            w.x = *(uint32_t*)&a;
            w.y = *(uint32_t*)&b;
            *(uint2*)&g_Woutp[(size_t)(k >> 6) * VSZ * PAD_E +
                              (size_t)v * PAD_E + (k & 63)] = w;
        }
    } else if (bid < 4256) {
        int n = bid - 4000;
        int k = tid;
        float x = W1[k * Hd + n];
        g_W1p[(k >> 6) * CH_HALF_E + n * PAD_E + (k & 63)] = __float2half_rn(x);
    } else {
        int wb = bid - 4256;
        int n0 = (wb & 3) * 64;
        int b0 = (wb >> 2) * 16;
        __shared__ float sh[16][260];
        for (int i = tid; i < 16 * 256; i += 256) {
            int bb = i >> 8;
            int k = i & 255;
            sh[bb][k] = hidden[(size_t)(Bd + b0 + bb) * Hd + k];
        }
        __syncthreads();
        int nn = tid & 63;
        int bq = tid >> 6;
        float acc[4] = {0.f, 0.f, 0.f, 0.f};
#pragma unroll 8
        for (int j = 0; j < 256; j++) {
            float w = W2[j * Hd + n0 + nn];
#pragma unroll
            for (int u = 0; u < 4; u++) acc[u] += sh[bq + 4 * u][j] * w;
        }
        float bias = b2[n0 + nn];
#pragma unroll
        for (int u = 0; u < 4; u++)
            g_w2h[(size_t)(b0 + bq + 4 * u) * Hd + n0 + nn] = acc[u] + bias;
    }
}

// ---------------- K2: scores + local softmax + partial Xa numerator -------
#define SA_HI 0
#define SB_OFF 33792
#define SB_STRIDE 36864
#define SC_SMEM (33792 + 2 * 36864)
__global__ __launch_bounds__(256, 2)
void scores_mma_kernel(const float* __restrict__ enc,
                       const float* __restrict__ Vv) {
    extern __shared__ __align__(16) char smem[];
    const uint32_t sm_b = smem_u32(smem);
    const int tid = threadIdx.x;
    const int wid = tid >> 5;
    const int lane = tid & 31;
    const int g = lane >> 2;
    const int t = lane & 3;
    const int wm = wid >> 2;
    const int wn = wid & 3;
    const int quad = lane >> 3;
    const int r8 = lane & 7;
    const int b = blockIdx.x >> 5;
    const int chunk = blockIdx.x & (NCH - 1);
    const int m0 = blockIdx.x * 64;
    const float* encb = enc + (size_t)m0 * Hd;

    float acc[2][8][4];
#pragma unroll
    for (int f = 0; f < 2; f++)
#pragma unroll
        for (int j = 0; j < 8; j++)
#pragma unroll
            for (int q = 0; q < 4; q++) acc[f][j][q] = 0.f;

    uint32_t aaddr[2];
#pragma unroll
    for (int f = 0; f < 2; f++)
        aaddr[f] = sm_b + (wm * 32 + f * 16 + ((quad & 1) << 3) + r8) * 528
                 + ((quad >> 1) << 4);
    uint32_t bbase[4];
#pragma unroll
    for (int jj = 0; jj < 4; jj++)
        bbase[jj] = (wn * 64 + jj * 16 + ((quad >> 1) << 3) + r8) * 144
                  + ((quad & 1) << 4);

    {
        const char* src = (const char*)g_W1p;
#pragma unroll
        for (int i = 0; i < 9; i++) {
            int idx = tid + i * 256;
            cp16(sm_b + SB_OFF + idx * 16, src + idx * 16);
        }
        cp_commit();
    }
    {
#pragma unroll
        for (int i = 0; i < 16; i++) {
            int idx = tid + i * 256;
            int row = idx >> 6;
            int kp = idx & 63;
            float4 v = *(const float4*)(encb + (size_t)row * Hd + kp * 4);
            __half2 h0 = {__float2half_rn(v.x), __float2half_rn(v.y)};
            __half2 h1 = {__float2half_rn(v.z), __float2half_rn(v.w)};
            uint2 w;
            w.x = *(uint32_t*)&h0;
            w.y = *(uint32_t*)&h1;
            *(uint2*)(smem + SA_HI + row * 528 + kp * 8) = w;
        }
    }

#pragma unroll
    for (int c = 0; c < 4; c++) {
        if (c < 3) {
            const char* src = (const char*)(g_W1p + (size_t)(c + 1) * CH_HALF_E);
            uint32_t dst = sm_b + SB_OFF + ((c + 1) & 1) * SB_STRIDE;
#pragma unroll
            for (int i = 0; i < 9; i++) {
                int idx = tid + i * 256;
                cp16(dst + idx * 16, src + idx * 16);
            }
            cp_commit();
            cp_wait<1>();
        } else {
            cp_wait<0>();
        }
        __syncthreads();

        const uint32_t buf = sm_b + SB_OFF + (c & 1) * SB_STRIDE;
#pragma unroll
        for (int ks = 0; ks < 4; ks++) {
            uint32_t af[2][4];
#pragma unroll
            for (int f = 0; f < 2; f++)
                ldsm_x4(af[f], aaddr[f] + c * 128 + ks * 32);
#pragma unroll
            for (int jj = 0; jj < 4; jj++) {
                uint32_t bf[4];
                ldsm_x4(bf, buf + bbase[jj] + ks * 32);
                mma_fp16(acc[0][2 * jj], af[0], bf[0], bf[1]);
                mma_fp16(acc[1][2 * jj], af[1], bf[0], bf[1]);
                mma_fp16(acc[0][2 * jj + 1], af[0], bf[2], bf[3]);
                mma_fp16(acc[1][2 * jj + 1], af[1], bf[2], bf[3]);
            }
        }
        __syncthreads();
    }

    float* EP = (float*)(smem + SB_OFF);
    float* sw2 = EP;
    float* sV = EP + 256;
    float* sp = EP + 512;
    float* red = EP + 768;
    float* e_arr = EP + 832;
    sw2[tid] = g_w2h[b * Hd + tid];
    sV[tid] = Vv[tid];
    __syncthreads();

    float p[2][2] = {{0.f, 0.f}, {0.f, 0.f}};
#pragma unroll
    for (int f = 0; f < 2; f++)
#pragma unroll
        for (int j = 0; j < 8; j++) {
            int cc = wn * 64 + 8 * j + 2 * t;
            float v0 = sV[cc], v1 = sV[cc + 1];
            float w0 = sw2[cc], w1 = sw2[cc + 1];
            p[f][0] += v0 * fast_tanh(acc[f][j][0] + w0)
                     + v1 * fast_tanh(acc[f][j][1] + w1);
            p[f][1] += v0 * fast_tanh(acc[f][j][2] + w0)
                     + v1 * fast_tanh(acc[f][j][3] + w1);
        }
#pragma unroll
    for (int f = 0; f < 2; f++)
#pragma unroll
        for (int u = 0; u < 2; u++) {
            float v = p[f][u];
            v += __shfl_xor_sync(0xffffffffu, v, 1);
            v += __shfl_xor_sync(0xffffffffu, v, 2);
            if (t == 0) {
                int r = wm * 32 + f * 16 + g + 8 * u;
                sp[wn * 64 + r] = v;
            }
        }
    __syncthreads();

    float sc = 0.f;
    if (tid < 64) {
        sc = sp[tid] + sp[64 + tid] + sp[128 + tid] + sp[192 + tid];
        red[tid] = sc;
    }
    __syncthreads();
    for (int d = 32; d > 0; d >>= 1) {
        if (tid < d) red[tid] = fmaxf(red[tid], red[tid + d]);
        __syncthreads();
    }
    float mloc = red[0];
    __syncthreads();
    if (tid < 64) {
        float e = expf(sc - mloc);
        e_arr[tid] = e;
        red[tid] = e;
    }
    __syncthreads();
    for (int d = 32; d > 0; d >>= 1) {
        if (tid < d) red[tid] += red[tid + d];
        __syncthreads();
    }
    if (tid == 0) {
        g_mz[2 * blockIdx.x] = mloc;
        g_mz[2 * blockIdx.x + 1] = red[0];
    }
    __syncthreads();

    float a2 = 0.f;
#pragma unroll 8
    for (int s = 0; s < 64; s++) {
        __half hv = *(const __half*)(smem + SA_HI + s * 528 + tid * 2);
        a2 += e_arr[s] * __half2float(hv);
    }
    g_XaP[((size_t)chunk * Bd + b) * Hd + tid] = a2;
}

// ---------------- K3: cat = [emb[inp]; Xa-combined] ----------------
__global__ void cat_kernel(const int* __restrict__ inp,
                           const float* __restrict__ emb) {
    const int b = blockIdx.x;
    const int tid = threadIdx.x;  // 256
    int token = inp[b];
    g_cat[b * 512 + tid] = emb[(size_t)token * Ed + tid];
    float M = -1e30f;
#pragma unroll
    for (int i = 0; i < NCH; i++)
        M = fmaxf(M, g_mz[2 * (b * NCH + i)]);
    float Z = 0.f, X = 0.f;
#pragma unroll
    for (int i = 0; i < NCH; i++) {
        float w = expf(g_mz[2 * (b * NCH + i)] - M);
        Z += w * g_mz[2 * (b * NCH + i) + 1];
        X += w * g_XaP[((size_t)i * Bd + b) * Hd + tid];
    }
    g_cat[b * 512 + 256 + tid] = X / Z;
}

// ---------------- K4: res = cat @ W3 + b3 (128 CTAs, 512 thr, k-split) ----
#define RES_SMEM ((16 * 524 + 16 * 520 + 512) * 4)
__global__ __launch_bounds__(512)
void res_kernel(const float* __restrict__ W3, const float* __restrict__ b3) {
    extern __shared__ float rsm[];
    float* w3t = rsm;                      // 16 x 524 [n][k]
    float* cs = rsm + 16 * 524;            // 16 x 520 [b][k]
    float* part = rsm + 16 * 524 + 16 * 520;  // 512 partials
    const int n0 = (blockIdx.x & 15) * 16;
    const int bt = blockIdx.x >> 4;
    const int tid = threadIdx.x;
    const int o = tid & 255;               // output index (16b x 16n)
    const int half = tid >> 8;             // k-half
    const int nn = o & 15;
    const int bq = o >> 4;

    for (int idx = tid; idx < 2048; idx += 512) {
        int k = idx >> 2;
        int u = idx & 3;
        float4 w = *(const float4*)(W3 + (size_t)k * Hd + n0 + u * 4);
        w3t[(u * 4 + 0) * 524 + k] = w.x;
        w3t[(u * 4 + 1) * 524 + k] = w.y;
        w3t[(u * 4 + 2) * 524 + k] = w.z;
        w3t[(u * 4 + 3) * 524 + k] = w.w;
    }
    for (int idx = tid; idx < 16 * 512; idx += 512) {
        int bb = idx >> 9;
        int k = idx & 511;
        cs[bb * 520 + k] = g_cat[(size_t)(bt * 16 + bb) * 512 + k];
    }
    __syncthreads();

    float a0 = 0.f, a1 = 0.f, a2 = 0.f, a3 = 0.f;
    const int kbase = half * 64;           // in float4 units: 64 per half
#pragma unroll 8
    for (int k4 = 0; k4 < 64; k4++) {
        float4 cv = *(const float4*)&cs[bq * 520 + (kbase + k4) * 4];
        float4 wv = *(const float4*)&w3t[nn * 524 + (kbase + k4) * 4];
        a0 += cv.x * wv.x;
        a1 += cv.y * wv.y;
        a2 += cv.z * wv.z;
        a3 += cv.w * wv.w;
    }
    part[tid] = (a0 + a1) + (a2 + a3);
    __syncthreads();
    if (tid < 256)
        g_res[(size_t)(bt * 16 + bq) * Hd + n0 + nn] =
            part[tid] + part[tid + 256] + b3[n0 + nn];
}

// ---------------- K5: GRU gate GEMVs; cell 1 inlines combine0 -------------
__global__ __launch_bounds__(512)
void gru_gates_kernel(const float* __restrict__ hidden,
                      const float* __restrict__ Wih,
                      const float* __restrict__ Whh,
                      const float* __restrict__ bih,
                      const float* __restrict__ bhh,
                      int cell,
                      float* __restrict__ hid_out) {
    const int n0 = blockIdx.x * 64;
    const int b0 = blockIdx.y * 16;
    const int tid = threadIdx.x;
    __shared__ float xs[16][260], hs[16][260];
    if (cell == 0) {
        for (int i = tid; i < 16 * 256; i += 512) {
            int bb = i >> 8;
            int k = i & 255;
            xs[bb][k] = g_res[(size_t)(b0 + bb) * Hd + k];
            hs[bb][k] = hidden[(size_t)(b0 + bb) * Hd + k];
        }
    } else {
        for (int i = tid; i < 16 * 256; i += 512) {
            int bb = i >> 8;
            int j = i & 255;
            int b = b0 + bb;
            float gir = g_gi[(size_t)b * 768 + j];
            float ghr = g_gh[(size_t)b * 768 + j];
            float giz = g_gi[(size_t)b * 768 + 256 + j];
            float ghz = g_gh[(size_t)b * 768 + 256 + j];
            float gin = g_gi[(size_t)b * 768 + 512 + j];
            float ghn = g_gh[(size_t)b * 768 + 512 + j];
            float r = 1.f / (1.f + expf(-(gir + ghr)));
            float z = 1.f / (1.f + expf(-(giz + ghz)));
            float n = tanhf(gin + r * ghn);
            float h = hidden[(size_t)b * Hd + j];
            float hn = (1.f - z) * n + z * h;
            xs[bb][j] = hn;
            hs[bb][j] = hidden[(size_t)(Bd + b) * Hd + j];
            if (blockIdx.x == 0) hid_out[(size_t)b * Hd + j] = hn;
        }
    }
    __syncthreads();
    const int bb = tid & 15;
    const int g2 = tid >> 4;
    float* gi_out = (cell == 0) ? g_gi : g_gi2;
    float* gh_out = (cell == 0) ? g_gh : g_gh2;
#pragma unroll
    for (int gg = 0; gg < 2; gg++) {
        int gr = n0 + g2 + gg * 32;
        const float4* wi = (const float4*)(Wih + (size_t)gr * Hd);
        const float4* wh = (const float4*)(Whh + (size_t)gr * Hd);
        float gi = bih[gr], gh = bhh[gr];
#pragma unroll 8
        for (int k4 = 0; k4 < 64; k4++) {
            float4 a = wi[k4];
            float4 c = wh[k4];
            float4 xv = *(const float4*)&xs[bb][k4 * 4];
            float4 hv = *(const float4*)&hs[bb][k4 * 4];
            gi += a.x * xv.x + a.y * xv.y + a.z * xv.z + a.w * xv.w;
            gh += c.x * hv.x + c.y * hv.y + c.z * hv.z + c.w * hv.w;
        }
        gi_out[(size_t)(b0 + bb) * 768 + gr] = gi;
        gh_out[(size_t)(b0 + bb) * 768 + gr] = gh;
    }
}

// ---------------- K6: combine cell 1 -> hid_out + fp16 h1 ----------------
__global__ void gru_combine1_kernel(const float* __restrict__ hidden,
                                    float* __restrict__ hid_out) {
    int idx = blockIdx.x * 512 + threadIdx.x;  // 32768
    int b = idx >> 8;
    int j = idx & 255;
    float gir = g_gi2[(size_t)b * 768 + j];
    float ghr = g_gh2[(size_t)b * 768 + j];
    float giz = g_gi2[(size_t)b * 768 + 256 + j];
    float ghz = g_gh2[(size_t)b * 768 + 256 + j];
    float gin = g_gi2[(size_t)b * 768 + 512 + j];
    float ghn = g_gh2[(size_t)b * 768 + 512 + j];
    float r = 1.f / (1.f + expf(-(gir + ghr)));
    float z = 1.f / (1.f + expf(-(giz + ghz)));
    float n = tanhf(gin + r * ghn);
    float h = hidden[(size_t)(Bd + b) * Hd + j];
    float hn = (1.f - z) * n + z * h;
    hid_out[(size_t)(Bd + b) * Hd + j] = hn;
    g_h1h[(size_t)b * Hd + j] = __float2half_rn(hn);
}

// ---------------- K7: logits via fp16 mma + ldmatrix + softmax partials ---
#define LSB_OFF 67584
#define LG_SMEM (67584 + 2 * 36864)
__global__ __launch_bounds__(512, 1)
void logits_mma_kernel(const float* __restrict__ bout,
                       float* __restrict__ out) {
    extern __shared__ __align__(16) char smem[];
    const uint32_t sm_b = smem_u32(smem);
    const int tid = threadIdx.x;
    const int wid = tid >> 5;
    const int lane = tid & 31;
    const int g = lane >> 2;
    const int t = lane & 3;
    const int wm = wid >> 2;
    const int wn = wid & 3;
    const int quad = lane >> 3;
    const int r8 = lane & 7;
    const int v0 = blockIdx.x * 256;

    float acc[2][8][4];
#pragma unroll
    for (int f = 0; f < 2; f++)
#pragma unroll
        for (int j = 0; j < 8; j++)
#pragma unroll
            for (int q = 0; q < 4; q++) acc[f][j][q] = 0.f;

    uint32_t aaddr[2];
#pragma unroll
    for (int f = 0; f < 2; f++)
        aaddr[f] = sm_b + (wm * 32 + f * 16 + ((quad & 1) << 3) + r8) * 528
                 + ((quad >> 1) << 4);
    uint32_t bbase[4];
#pragma unroll
    for (int jj = 0; jj < 4; jj++)
        bbase[jj] = (wn * 64 + jj * 16 + ((quad >> 1) << 3) + r8) * 144
                  + ((quad & 1) << 4);

    {
        const char* src = (const char*)(g_Woutp + (size_t)v0 * PAD_E);
#pragma unroll
        for (int i = 0; i < 5; i++) {
            int idx = tid + i * 512;
            if (idx < 2304) cp16(sm_b + LSB_OFF + idx * 16, src + idx * 16);
        }
        cp_commit();
    }
    {
        const uint32_t* src = (const uint32_t*)g_h1h;
#pragma unroll
        for (int i = 0; i < 32; i++) {
            int idx = tid + i * 512;
            int row = idx >> 7;
            int c32 = idx & 127;
            *(uint32_t*)(smem + row * 528 + c32 * 4) = src[idx];
        }
    }

#pragma unroll
    for (int c = 0; c < 4; c++) {
        if (c < 3) {
            const char* src =
                (const char*)(g_Woutp + ((size_t)(c + 1) * VSZ + v0) * PAD_E);
            uint32_t dst = sm_b + LSB_OFF + ((c + 1) & 1) * SB_STRIDE;
#pragma unroll
            for (int i = 0; i < 5; i++) {
                int idx = tid + i * 512;
                if (idx < 2304) cp16(dst + idx * 16, src + idx * 16);
            }
            cp_commit();
            cp_wait<1>();
        } else {
            cp_wait<0>();
        }
        __syncthreads();

        const uint32_t buf = sm_b + LSB_OFF + (c & 1) * SB_STRIDE;
#pragma unroll
        for (int ks = 0; ks < 4; ks++) {
            uint32_t af[2][4];
#pragma unroll
            for (int f = 0; f < 2; f++)
                ldsm_x4(af[f], aaddr[f] + c * 128 + ks * 32);
#pragma unroll
            for (int jj = 0; jj < 4; jj++) {
                uint32_t bf[4];
                ldsm_x4(bf, buf + bbase[jj] + ks * 32);
                mma_fp16(acc[0][2 * jj], af[0], bf[0], bf[1]);
                mma_fp16(acc[1][2 * jj], af[1], bf[0], bf[1]);
                mma_fp16(acc[0][2 * jj + 1], af[0], bf[2], bf[3]);
                mma_fp16(acc[1][2 * jj + 1], af[1], bf[2], bf[3]);
            }
        }
        __syncthreads();
    }

    float* stage = (float*)(smem + LSB_OFF);
    float rm = -1e30f, rs = 0.f;
#pragma unroll
    for (int cg = 0; cg < 4; cg++) {
        if (wn == cg) {
#pragma unroll
            for (int f = 0; f < 2; f++)
#pragma unroll
                for (int j = 0; j < 8; j++)
#pragma unroll
                    for (int q = 0; q < 4; q++) {
                        int row = wm * 32 + f * 16 + g + 8 * (q >> 1);
                        int col = 8 * j + 2 * t + (q & 1);
                        stage[row * 65 + col] = acc[f][j][q];
                    }
        }
        __syncthreads();
#pragma unroll
        for (int i = 0; i < 16; i++) {
            int idx = tid + i * 512;
            int row = idx >> 6;
            int col = idx & 63;
            out[(size_t)row * VSZ + v0 + cg * 64 + col] =
                stage[row * 65 + col] + bout[v0 + cg * 64 + col];
        }
        if (tid < 128) {
            float lm = rm;
            for (int col = 0; col < 64; col++)
                lm = fmaxf(lm, stage[tid * 65 + col] + bout[v0 + cg * 64 + col]);
            float sc = rs * expf(rm - lm);
            for (int col = 0; col < 64; col++)
                sc += expf(stage[tid * 65 + col] + bout[v0 + cg * 64 + col] - lm);
            rm = lm;
            rs = sc;
        }
        __syncthreads();
    }
    if (tid < 128) {
        g_lmz[(tid * NVB + blockIdx.x) * 2] = rm;
        g_lmz[(tid * NVB + blockIdx.x) * 2 + 1] = rs;
    }
}

// ---------------- K8: log_softmax via partials (single pass) --------------
__global__ __launch_bounds__(1024)
void logsoftmax_kernel(float* __restrict__ out) {
    const int b = blockIdx.x;
    const int tid = threadIdx.x;
    __shared__ float red[1024];
    float4* row4 = (float4*)(out + (size_t)b * VSZ);

    float lm = -1e30f;
    if (tid < NVB) lm = g_lmz[(b * NVB + tid) * 2];
    red[tid] = lm;
    __syncthreads();
    for (int d = 512; d > 0; d >>= 1) {
        if (tid < d) red[tid] = fmaxf(red[tid], red[tid + d]);
        __syncthreads();
    }
    float M = red[0];
    __syncthreads();
    float sv = 0.f;
    if (tid < NVB)
        sv = g_lmz[(b * NVB + tid) * 2 + 1] * expf(lm - M);
    red[tid] = sv;
    __syncthreads();
    for (int d = 512; d > 0; d >>= 1) {
        if (tid < d) red[tid] += red[tid + d];
        __syncthreads();
    }
    float lse = M + logf(red[0]);
    for (int v = tid; v < 8000; v += 1024) {
        float4 x = row4[v];
        x.x -= lse; x.y -= lse; x.z -= lse; x.w -= lse;
        row4[v] = x;
    }
}

// ---------------- launch ----------------
extern "C" void kernel_launch(void* const* d_in, const int* in_sizes, int n_in,
                              void* d_out, int out_size) {
    const int* inp = (const int*)d_in[0];
    const float* hidden = (const float*)d_in[1];
    const float* enc = (const float*)d_in[2];
    const float* emb = (const float*)d_in[3];
    const float* W1 = (const float*)d_in[4];
    const float* W2 = (const float*)d_in[5];
    const float* W3 = (const float*)d_in[6];
    const float* b2 = (const float*)d_in[7];
    const float* b3 = (const float*)d_in[8];
    const float* V = (const float*)d_in[9];
    const float* Wih0 = (const float*)d_in[10];
    const float* Whh0 = (const float*)d_in[11];
    const float* bih0 = (const float*)d_in[12];
    const float* bhh0 = (const float*)d_in[13];
    const float* Wih1 = (const float*)d_in[14];
    const float* Whh1 = (const float*)d_in[15];
    const float* bih1 = (const float*)d_in[16];
    const float* bhh1 = (const float*)d_in[17];
    const float* Wout = (const float*)d_in[18];
    const float* bout = (const float*)d_in[19];

    float* out = (float*)d_out;
    float* hid_out = out + (size_t)Bd * VSZ;

    cudaFuncSetAttribute(scores_mma_kernel,
                         cudaFuncAttributeMaxDynamicSharedMemorySize, SC_SMEM);
    cudaFuncSetAttribute(logits_mma_kernel,
                         cudaFuncAttributeMaxDynamicSharedMemorySize, LG_SMEM);
    cudaFuncSetAttribute(res_kernel,
                         cudaFuncAttributeMaxDynamicSharedMemorySize, RES_SMEM);

    prep_merge_kernel<<<4288, 256>>>(W1, Wout, hidden, W2, b2);
    scores_mma_kernel<<<Bd * NCH, 256, SC_SMEM>>>(enc, V);
    cat_kernel<<<Bd, 256>>>(inp, emb);
    res_kernel<<<128, 512, RES_SMEM>>>(W3, b3);
    gru_gates_kernel<<<dim3(12, 8), 512>>>(hidden, Wih0, Whh0, bih0, bhh0,
                                           0, hid_out);
    gru_gates_kernel<<<dim3(12, 8), 512>>>(hidden, Wih1, Whh1, bih1, bhh1,
                                           1, hid_out);
    gru_combine1_kernel<<<64, 512>>>(hidden, hid_out);
    logits_mma_kernel<<<NVB, 512, LG_SMEM>>>(bout, out);
    logsoftmax_kernel<<<Bd, 1024>>>(out);
}